// round 1
// baseline (speedup 1.0000x reference)
#include <cuda_runtime.h>
#include <cuda_bf16.h>

#define IN_DIM  2048
#define HDIM    8192
#define OUT_DIM 512
#define NBATCH  4096

// ---------------- scratch (static __device__ per harness rules) ----------------
__device__ float g_W1 [(size_t)IN_DIM * HDIM];     //  64 MB  W1 dequant [IN,H]
__device__ float g_W1T[(size_t)HDIM  * IN_DIM];    //  64 MB  W1^T      [H,IN]
__device__ float g_W2 [(size_t)HDIM  * OUT_DIM];   //  16 MB  W2        [H,OUT]
__device__ float g_W2T[(size_t)OUT_DIM * HDIM];    //  16 MB  W2^T      [OUT,H]
__device__ float g_z1 [(size_t)NBATCH * HDIM];     // 128 MB  c19(x@W1+b1)
__device__ float g_t  [(size_t)NBATCH * HDIM];     // 128 MB  z@W2^T+db1
__device__ int   g_maskmode;

// ---------------- mask dtype detection ----------------
// jax bool may arrive as u8 / i32 / f32 / bf16 / f16 depending on harness
// conversion. Detect from the raw bit patterns of the first 16KB.
__global__ void detect_mask_kernel(const unsigned int* __restrict__ m, int nwords) {
    __shared__ int ok[4]; // 0:i32 1:f32 2:bf16 3:f16
    if (threadIdx.x < 4) ok[threadIdx.x] = 1;
    __syncthreads();
    for (int i = threadIdx.x; i < nwords; i += blockDim.x) {
        unsigned w = m[i];
        if (!(w == 0u || w == 1u))              atomicAnd(&ok[0], 0);
        if (!(w == 0u || w == 0x3F800000u))     atomicAnd(&ok[1], 0);
        unsigned lo = w & 0xFFFFu, hi = w >> 16;
        if (!((lo == 0u || lo == 0x3F80u) && (hi == 0u || hi == 0x3F80u)))
            atomicAnd(&ok[2], 0);
        if (!((lo == 0u || lo == 0x3C00u) && (hi == 0u || hi == 0x3C00u)))
            atomicAnd(&ok[3], 0);
    }
    __syncthreads();
    if (threadIdx.x == 0) {
        int mode = 0;                   // default: u8
        if      (ok[0]) mode = 1;       // int32
        else if (ok[1]) mode = 2;       // float32
        else if (ok[2]) mode = 3;       // bf16
        else if (ok[3]) mode = 4;       // f16
        g_maskmode = mode;
    }
}

__device__ __forceinline__ int read_mask(const void* p, long i, int mode) {
    switch (mode) {
        case 1:  return ((const int*)p)[i] != 0;
        case 2:  return ((const float*)p)[i] != 0.0f;
        case 3:  return ((const unsigned short*)p)[i] != 0;
        case 4:  return ((const unsigned short*)p)[i] != 0;
        default: return ((const unsigned char*)p)[i] != 0;
    }
}

// ---------------- dequant + transpose (32x32 tiles) ----------------
__global__ void dequant_kernel(const int* __restrict__ idx, const void* __restrict__ mask,
                               const float* __restrict__ wf, const float* __restrict__ cb,
                               float* __restrict__ W, float* __restrict__ WT,
                               int R, int C) {
    __shared__ float tile[32][33];
    const int mode = g_maskmode;
    const int c0 = blockIdx.x * 32;
    const int r0 = blockIdx.y * 32;
    for (int rr = threadIdx.y; rr < 32; rr += 8) {
        long off = (long)(r0 + rr) * C + c0 + threadIdx.x;
        int  m = read_mask(mask, off, mode);
        float v = m ? cb[idx[off]] : wf[off];
        W[off] = v;
        tile[rr][threadIdx.x] = v;
    }
    __syncthreads();
    for (int rr = threadIdx.y; rr < 32; rr += 8) {
        WT[(long)(c0 + rr) * R + r0 + threadIdx.x] = tile[threadIdx.x][rr];
    }
}

// ---------------- c19 activation (exact jax fp32 semantics) ----------------
__device__ __forceinline__ float c19f(float x, float craw, float rhoraw) {
    float c   = fmaxf(craw, 0.1f);
    float rho = fmaxf(rhoraw, 0.0f);
    float L   = 6.0f * c;
    float s   = x / c;
    float n   = floorf(s);
    float t   = s - n;
    float h   = t * (1.0f - t);
    float sgn = (fmodf(n, 2.0f) == 0.0f) ? 1.0f : -1.0f;
    float interior = c * (sgn * h + rho * h * h);
    return (x >= L) ? (x - L) : ((x <= -L) ? (x + L) : interior);
}

// ---------------- packed f32x2 helpers (2x FFMA throughput vs FFMA-3reg) ----------------
typedef unsigned long long u64;
__device__ __forceinline__ u64 pack2(float lo, float hi) {
    u64 r; asm("mov.b64 %0, {%1, %2};" : "=l"(r) : "f"(lo), "f"(hi)); return r;
}
__device__ __forceinline__ void ffma2(u64 &c, u64 a, u64 b) {
    asm("fma.rn.f32x2 %0, %1, %2, %0;" : "+l"(c) : "l"(a), "l"(b));
}
__device__ __forceinline__ void unpack2(u64 v, float &lo, float &hi) {
    asm("mov.b64 {%0, %1}, %2;" : "=f"(lo), "=f"(hi) : "l"(v));
}

// ---------------- SGEMM: C[M,N] = A[M,K] (rm) * B[K,N] (rm) + bias[n], opt c19 ----------------
#define BM 128
#define BN 128
#define BK 16

__global__ void __launch_bounds__(256, 2)
sgemm_kernel(const float* __restrict__ A, const float* __restrict__ B,
             float* __restrict__ C, int M, int Nn, int K,
             const float* __restrict__ bias, int epi,
             const float* __restrict__ craw, const float* __restrict__ rhoraw) {
    __shared__ float As[BK][BM];
    __shared__ float Bs[BK][BN];
    const int tid  = threadIdx.x;
    const int trow = tid >> 4;   // 0..15
    const int tcol = tid & 15;   // 0..15
    const long aBase    = (long)blockIdx.y * BM * K;
    const long bColBase = (long)blockIdx.x * BN;

    const int aRow = tid >> 2;   // 0..63
    const int aC4  = tid & 3;    // 0..3
    const int bRow = tid >> 5;   // 0..7
    const int bC4  = tid & 31;   // 0..31

    u64 acc[8][4];
#pragma unroll
    for (int i = 0; i < 8; i++)
#pragma unroll
        for (int j = 0; j < 4; j++) acc[i][j] = 0ull;

    for (int k0 = 0; k0 < K; k0 += BK) {
#pragma unroll
        for (int i = 0; i < 2; i++) {
            int r = aRow + i * 64;
            float4 v = *(const float4*)(A + aBase + (long)r * K + k0 + aC4 * 4);
            As[aC4 * 4 + 0][r] = v.x;
            As[aC4 * 4 + 1][r] = v.y;
            As[aC4 * 4 + 2][r] = v.z;
            As[aC4 * 4 + 3][r] = v.w;
        }
#pragma unroll
        for (int i = 0; i < 2; i++) {
            int r = bRow + i * 8;
            *(float4*)&Bs[r][bC4 * 4] =
                *(const float4*)(B + (long)(k0 + r) * Nn + bColBase + bC4 * 4);
        }
        __syncthreads();
#pragma unroll
        for (int kk = 0; kk < BK; kk++) {
            float4 a0 = *(const float4*)&As[kk][trow * 8];
            float4 a1 = *(const float4*)&As[kk][trow * 8 + 4];
            const u64* bp = (const u64*)&Bs[kk][tcol * 8];
            u64 b0 = bp[0], b1 = bp[1], b2 = bp[2], b3 = bp[3];
            u64 a2[8];
            a2[0] = pack2(a0.x, a0.x); a2[1] = pack2(a0.y, a0.y);
            a2[2] = pack2(a0.z, a0.z); a2[3] = pack2(a0.w, a0.w);
            a2[4] = pack2(a1.x, a1.x); a2[5] = pack2(a1.y, a1.y);
            a2[6] = pack2(a1.z, a1.z); a2[7] = pack2(a1.w, a1.w);
#pragma unroll
            for (int i = 0; i < 8; i++) {
                ffma2(acc[i][0], a2[i], b0);
                ffma2(acc[i][1], a2[i], b1);
                ffma2(acc[i][2], a2[i], b2);
                ffma2(acc[i][3], a2[i], b3);
            }
        }
        __syncthreads();
    }

    const long cBase = (long)blockIdx.y * BM * Nn + bColBase;
#pragma unroll
    for (int i = 0; i < 8; i++) {
        int row = trow * 8 + i;
#pragma unroll
        for (int j = 0; j < 4; j++) {
            int col = tcol * 8 + j * 2;
            long gn = bColBase + col;
            float lo, hi;
            unpack2(acc[i][j], lo, hi);
            lo += bias[gn];
            hi += bias[gn + 1];
            if (epi) {
                lo = c19f(lo, craw[gn],     rhoraw[gn]);
                hi = c19f(hi, craw[gn + 1], rhoraw[gn + 1]);
            }
            C[cBase + (long)row * Nn + col]     = lo;
            C[cBase + (long)row * Nn + col + 1] = hi;
        }
    }
}

// ---------------- launch ----------------
extern "C" void kernel_launch(void* const* d_in, const int* in_sizes, int n_in,
                              void* d_out, int out_size) {
    const float* x    = (const float*)d_in[0];
    const float* cb1  = (const float*)d_in[1];
    const float* cb2  = (const float*)d_in[2];
    const float* W1f  = (const float*)d_in[3];
    const float* W2f  = (const float*)d_in[4];
    const float* b1   = (const float*)d_in[5];
    const float* b2   = (const float*)d_in[6];
    const float* db1  = (const float*)d_in[7];
    const float* db2  = (const float*)d_in[8];
    const float* craw = (const float*)d_in[9];
    const float* rraw = (const float*)d_in[10];
    const int*   W1i  = (const int*)d_in[11];
    const int*   W2i  = (const int*)d_in[12];
    const void*  W1m  = d_in[13];
    const void*  W2m  = d_in[14];

    float *pW1, *pW1T, *pW2, *pW2T, *pz1, *pt;
    cudaGetSymbolAddress((void**)&pW1,  g_W1);
    cudaGetSymbolAddress((void**)&pW1T, g_W1T);
    cudaGetSymbolAddress((void**)&pW2,  g_W2);
    cudaGetSymbolAddress((void**)&pW2T, g_W2T);
    cudaGetSymbolAddress((void**)&pz1,  g_z1);
    cudaGetSymbolAddress((void**)&pt,   g_t);

    float* dec = (float*)d_out;                                   // [N, IN_DIM]
    float* z   = (float*)d_out + (size_t)NBATCH * IN_DIM;         // [N, OUT_DIM]

    // 1. mask dtype probe (both masks share dtype)
    detect_mask_kernel<<<1, 256>>>((const unsigned int*)W1m, 4096);

    // 2. dequant + transpose
    dequant_kernel<<<dim3(HDIM / 32, IN_DIM / 32), dim3(32, 8)>>>(
        W1i, W1m, W1f, cb1, pW1, pW1T, IN_DIM, HDIM);
    dequant_kernel<<<dim3(OUT_DIM / 32, HDIM / 32), dim3(32, 8)>>>(
        W2i, W2m, W2f, cb2, pW2, pW2T, HDIM, OUT_DIM);

    // 3. G1: z1 = c19(x @ W1 + b1)          [4096, 8192]
    sgemm_kernel<<<dim3(HDIM / BN, NBATCH / BM), 256>>>(
        x, pW1, pz1, NBATCH, HDIM, IN_DIM, b1, 1, craw, rraw);

    // 4. G2: z = z1 @ W2 + b2               [4096, 512] -> output
    sgemm_kernel<<<dim3(OUT_DIM / BN, NBATCH / BM), 256>>>(
        pz1, pW2, z, NBATCH, OUT_DIM, HDIM, b2, 0, nullptr, nullptr);

    // 5. G3: t = z @ W2^T + db1             [4096, 8192]
    sgemm_kernel<<<dim3(HDIM / BN, NBATCH / BM), 256>>>(
        z, pW2T, pt, NBATCH, HDIM, OUT_DIM, db1, 0, nullptr, nullptr);

    // 6. G4: dec = t @ W1^T + db2           [4096, 2048] -> output
    sgemm_kernel<<<dim3(IN_DIM / BN, NBATCH / BM), 256>>>(
        pt, pW1T, dec, NBATCH, IN_DIM, HDIM, db2, 0, nullptr, nullptr);
}

// round 4
// speedup vs baseline: 1.5975x; 1.5975x over previous
#include <cuda_runtime.h>
#include <cuda_bf16.h>
#include <cstdint>

#define IN_DIM  2048
#define HDIM    8192
#define OUT_DIM 512
#define NBATCH  4096

typedef __nv_bfloat16 bf16;

// ---------------- scratch (static __device__ per harness rules) ----------------
__device__ __align__(256) bf16 g_xhi [(size_t)NBATCH * IN_DIM];
__device__ __align__(256) bf16 g_xlo [(size_t)NBATCH * IN_DIM];
__device__ __align__(256) bf16 g_W1hi[(size_t)IN_DIM * HDIM];
__device__ __align__(256) bf16 g_W1lo[(size_t)IN_DIM * HDIM];
__device__ __align__(256) bf16 g_W1Thi[(size_t)HDIM * IN_DIM];
__device__ __align__(256) bf16 g_W1Tlo[(size_t)HDIM * IN_DIM];
__device__ __align__(256) bf16 g_W2hi[(size_t)HDIM * OUT_DIM];
__device__ __align__(256) bf16 g_W2lo[(size_t)HDIM * OUT_DIM];
__device__ __align__(256) bf16 g_W2Thi[(size_t)OUT_DIM * HDIM];
__device__ __align__(256) bf16 g_W2Tlo[(size_t)OUT_DIM * HDIM];
__device__ __align__(256) bf16 g_z1hi[(size_t)NBATCH * HDIM];
__device__ __align__(256) bf16 g_z1lo[(size_t)NBATCH * HDIM];
__device__ __align__(256) bf16 g_zhi [(size_t)NBATCH * OUT_DIM];
__device__ __align__(256) bf16 g_zlo [(size_t)NBATCH * OUT_DIM];
__device__ __align__(256) bf16 g_thi [(size_t)NBATCH * HDIM];
__device__ __align__(256) bf16 g_tlo [(size_t)NBATCH * HDIM];
__device__ int g_maskmode;

// ---------------- PTX helpers (compute_100-safe: sm_80-era features only) ----
__device__ __forceinline__ uint32_t smem_u32(const void* p) {
    uint32_t a;
    asm("{ .reg .u64 t; cvta.to.shared.u64 t, %1; cvt.u32.u64 %0, t; }" : "=r"(a) : "l"(p));
    return a;
}
// XOR swizzle: bits[6:4] ^= bits[9:7]  (conflict-free ldmatrix on 64B rows,
// tile base must be 1024B aligned)
#define SWZ128(off) ((off) ^ (((off) >> 3) & 0x70))

__device__ __forceinline__ void cp16(uint32_t dst, const void* src) {
    asm volatile("cp.async.cg.shared.global [%0], [%1], 16;" :: "r"(dst), "l"(src));
}
#define CP_COMMIT() asm volatile("cp.async.commit_group;" ::: "memory")
#define CP_WAIT(n)  asm volatile("cp.async.wait_group %0;" :: "n"(n) : "memory")

__device__ __forceinline__ void ldsm4(uint32_t a, uint32_t& r0, uint32_t& r1,
                                      uint32_t& r2, uint32_t& r3) {
    asm volatile("ldmatrix.sync.aligned.m8n8.x4.shared.b16 {%0,%1,%2,%3}, [%4];"
                 : "=r"(r0), "=r"(r1), "=r"(r2), "=r"(r3) : "r"(a));
}

__device__ __forceinline__ void mma16816(float* d, const uint32_t* a, const uint32_t* b) {
    asm volatile("mma.sync.aligned.m16n8k16.row.col.f32.bf16.bf16.f32 "
        "{%0,%1,%2,%3}, {%4,%5,%6,%7}, {%8,%9}, {%0,%1,%2,%3};"
        : "+f"(d[0]), "+f"(d[1]), "+f"(d[2]), "+f"(d[3])
        : "r"(a[0]), "r"(a[1]), "r"(a[2]), "r"(a[3]), "r"(b[0]), "r"(b[1]));
}

// ---------------- mask dtype detection ----------------
__global__ void detect_mask_kernel(const unsigned int* __restrict__ m, int nwords) {
    __shared__ int ok[4];
    if (threadIdx.x < 4) ok[threadIdx.x] = 1;
    __syncthreads();
    for (int i = threadIdx.x; i < nwords; i += blockDim.x) {
        unsigned w = m[i];
        if (!(w == 0u || w == 1u))          atomicAnd(&ok[0], 0);
        if (!(w == 0u || w == 0x3F800000u)) atomicAnd(&ok[1], 0);
        unsigned lo = w & 0xFFFFu, hi = w >> 16;
        if (!((lo == 0u || lo == 0x3F80u) && (hi == 0u || hi == 0x3F80u))) atomicAnd(&ok[2], 0);
        if (!((lo == 0u || lo == 0x3C00u) && (hi == 0u || hi == 0x3C00u))) atomicAnd(&ok[3], 0);
    }
    __syncthreads();
    if (threadIdx.x == 0) {
        int mode = 0;
        if      (ok[0]) mode = 1;
        else if (ok[1]) mode = 2;
        else if (ok[2]) mode = 3;
        else if (ok[3]) mode = 4;
        g_maskmode = mode;
    }
}

__device__ __forceinline__ int read_mask(const void* p, long i, int mode) {
    switch (mode) {
        case 1:  return ((const int*)p)[i] != 0;
        case 2:  return ((const float*)p)[i] != 0.0f;
        case 3:  return ((const unsigned short*)p)[i] != 0;
        case 4:  return ((const unsigned short*)p)[i] != 0;
        default: return ((const unsigned char*)p)[i] != 0;
    }
}

__device__ __forceinline__ void split2(float v, bf16& h, bf16& l) {
    h = __float2bfloat16(v);
    l = __float2bfloat16(v - __bfloat162float(h));
}

// ---------------- split x ----------------
__global__ void split_kernel(const float* __restrict__ src, bf16* __restrict__ hi,
                             bf16* __restrict__ lo, size_t n) {
    size_t i = (size_t)blockIdx.x * blockDim.x + threadIdx.x;
    if (i < n) {
        bf16 h, l;
        split2(src[i], h, l);
        hi[i] = h; lo[i] = l;
    }
}

// ---------------- dequant + split + transpose ----------------
__global__ void dequant_split_kernel(const int* __restrict__ idx, const void* __restrict__ mask,
                                     const float* __restrict__ wf, const float* __restrict__ cb,
                                     bf16* __restrict__ Whi, bf16* __restrict__ Wlo,
                                     bf16* __restrict__ WThi, bf16* __restrict__ WTlo,
                                     int R, int C) {
    __shared__ float tile[32][33];
    const int mode = g_maskmode;
    const int c0 = blockIdx.x * 32;
    const int r0 = blockIdx.y * 32;
    for (int rr = threadIdx.y; rr < 32; rr += 8) {
        long off = (long)(r0 + rr) * C + c0 + threadIdx.x;
        int  m = read_mask(mask, off, mode);
        float v = m ? cb[idx[off]] : wf[off];
        bf16 h, l; split2(v, h, l);
        Whi[off] = h; Wlo[off] = l;
        tile[rr][threadIdx.x] = v;
    }
    __syncthreads();
    for (int rr = threadIdx.y; rr < 32; rr += 8) {
        float v = tile[threadIdx.x][rr];
        long off = (long)(c0 + rr) * R + r0 + threadIdx.x;
        bf16 h, l; split2(v, h, l);
        WThi[off] = h; WTlo[off] = l;
    }
}

// ---------------- c19 activation ----------------
__device__ __forceinline__ float c19f(float x, float craw, float rhoraw) {
    float c   = fmaxf(craw, 0.1f);
    float rho = fmaxf(rhoraw, 0.0f);
    float L   = 6.0f * c;
    float s   = x / c;
    float n   = floorf(s);
    float t   = s - n;
    float h   = t * (1.0f - t);
    float sgn = (fmodf(n, 2.0f) == 0.0f) ? 1.0f : -1.0f;
    float interior = c * (sgn * h + rho * h * h);
    return (x >= L) ? (x - L) : ((x <= -L) ? (x + L) : interior);
}

// ---------------- mma.sync split-bf16 GEMM ----------------
// C[M,Nn] = sum over 3 passes A_p[M,K] * B_p[Nn,K]^T  (B K-major: row n holds K)
// passes: (Ahi,Bhi), (Ahi,Blo), (Alo,Bhi)
// Block 128x128, BK=32. 8 warps: 2(M) x 4(N), warp tile 64x32. 4-stage cp.async.
#define BM 128
#define BN 128
#define BKK 32
#define NSTAGE 4
#define STAGE_BYTES (BM * 64 + BN * 64)   // 8KB A + 8KB B
#define SMEM_TOTAL  (1024 + NSTAGE * STAGE_BYTES)

__global__ void __launch_bounds__(256, 1)
gemm_split_kernel(const bf16* __restrict__ Ahi, const bf16* __restrict__ Alo,
                  const bf16* __restrict__ Bhi, const bf16* __restrict__ Blo,
                  int M, int Nn, int K,
                  const float* __restrict__ bias, int epi,
                  const float* __restrict__ craw, const float* __restrict__ rho,
                  float* __restrict__ Cf, bf16* __restrict__ Chi, bf16* __restrict__ Clo) {
    extern __shared__ char smem[];
    const uint32_t sbase = smem_u32(smem);
    const uint32_t tbase = (sbase + 1023u) & ~1023u;   // 1024B align for swizzle
    const int tid  = threadIdx.x;
    const int wid  = tid >> 5;
    const int lane = tid & 31;
    const int wm = wid & 1;          // 0..1 -> M offset wm*64
    const int wn = wid >> 1;         // 0..3 -> N offset wn*32

    const int m0 = blockIdx.y * BM;
    const int n0 = blockIdx.x * BN;

    uint32_t sA[NSTAGE], sB[NSTAGE];
#pragma unroll
    for (int s = 0; s < NSTAGE; s++) {
        sA[s] = tbase + s * STAGE_BYTES;
        sB[s] = sA[s] + BM * 64;
    }

    const int kchunks = K / BKK;
    const int ITERS = 3 * kchunks;

    float acc[4][4][4];
#pragma unroll
    for (int i = 0; i < 4; i++)
#pragma unroll
        for (int j = 0; j < 4; j++)
#pragma unroll
            for (int r = 0; r < 4; r++) acc[i][j][r] = 0.0f;

    // fill stage (it % NSTAGE) with k-chunk of pass p
    auto fill = [&](int it) {
        const int p  = it / kchunks;
        const int kc = it % kchunks;
        const bf16* Ap = (p == 2) ? Alo : Ahi;
        const bf16* Bp = (p == 1) ? Blo : Bhi;
        const int s = it % NSTAGE;
        const size_t k0 = (size_t)kc * BKK;
        // A: 128 rows x 4 chunks of 16B; B same. 2 chunks per thread each.
#pragma unroll
        for (int i = 0; i < 2; i++) {
            int ch = tid + i * 256;
            int r = ch >> 2, c = ch & 3;
            const char* srcA = (const char*)(Ap + (size_t)(m0 + r) * K + k0) + c * 16;
            cp16(sA[s] + SWZ128(r * 64 + c * 16), srcA);
            const char* srcB = (const char*)(Bp + (size_t)(n0 + r) * K + k0) + c * 16;
            cp16(sB[s] + SWZ128(r * 64 + c * 16), srcB);
        }
    };

    // prologue
    for (int it = 0; it < NSTAGE - 1; it++) { fill(it); CP_COMMIT(); }

    for (int it = 0; it < ITERS; it++) {
        CP_WAIT(NSTAGE - 2);
        __syncthreads();
        if (it + NSTAGE - 1 < ITERS) fill(it + NSTAGE - 1);
        CP_COMMIT();

        const int s = it % NSTAGE;
        const uint32_t Ab = sA[s], Bb = sB[s];
#pragma unroll
        for (int kk = 0; kk < 2; kk++) {      // two k16 steps per BK=32
            uint32_t af[4][4];
#pragma unroll
            for (int mi = 0; mi < 4; mi++) {
                int row = wm * 64 + mi * 16 + (lane & 15);
                int ch  = kk * 2 + (lane >> 4);
                ldsm4(Ab + SWZ128(row * 64 + ch * 16),
                      af[mi][0], af[mi][1], af[mi][2], af[mi][3]);
            }
            uint32_t bfr[4][2];
#pragma unroll
            for (int p = 0; p < 2; p++) {
                int g   = lane >> 3;                       // 8-lane group 0..3
                int ni  = p * 2 + (g >> 1);
                int row = wn * 32 + ni * 8 + (lane & 7);
                int ch  = kk * 2 + (g & 1);
                uint32_t r0, r1, r2, r3;
                ldsm4(Bb + SWZ128(row * 64 + ch * 16), r0, r1, r2, r3);
                bfr[p * 2][0] = r0;  bfr[p * 2][1] = r1;
                bfr[p * 2 + 1][0] = r2; bfr[p * 2 + 1][1] = r3;
            }
#pragma unroll
            for (int mi = 0; mi < 4; mi++)
#pragma unroll
                for (int ni = 0; ni < 4; ni++)
                    mma16816(acc[mi][ni], af[mi], bfr[ni]);
        }
    }

    // ---------------- epilogue: bias (+c19) + outputs ----------------
#pragma unroll
    for (int ni = 0; ni < 4; ni++) {
        const int n = n0 + wn * 32 + ni * 8 + 2 * (lane & 3);
        const float bv0 = __ldg(bias + n), bv1 = __ldg(bias + n + 1);
        float c0 = 0, c1 = 0, r0 = 0, r1 = 0;
        if (epi) {
            c0 = __ldg(craw + n);  c1 = __ldg(craw + n + 1);
            r0 = __ldg(rho + n);   r1 = __ldg(rho + n + 1);
        }
#pragma unroll
        for (int mi = 0; mi < 4; mi++) {
#pragma unroll
            for (int h = 0; h < 2; h++) {
                const int m = m0 + wm * 64 + mi * 16 + (lane >> 2) + h * 8;
                float v0 = acc[mi][ni][2 * h]     + bv0;
                float v1 = acc[mi][ni][2 * h + 1] + bv1;
                if (epi) { v0 = c19f(v0, c0, r0); v1 = c19f(v1, c1, r1); }
                const size_t off = (size_t)m * Nn + n;
                if (Cf) *(float2*)(Cf + off) = make_float2(v0, v1);
                if (Chi) {
                    bf16 h0, l0, h1, l1;
                    split2(v0, h0, l0); split2(v1, h1, l1);
                    *(__nv_bfloat162*)(Chi + off) = __nv_bfloat162(h0, h1);
                    *(__nv_bfloat162*)(Clo + off) = __nv_bfloat162(l0, l1);
                }
            }
        }
    }
}

// ---------------- launch ----------------
extern "C" void kernel_launch(void* const* d_in, const int* in_sizes, int n_in,
                              void* d_out, int out_size) {
    const float* x    = (const float*)d_in[0];
    const float* cb1  = (const float*)d_in[1];
    const float* cb2  = (const float*)d_in[2];
    const float* W1f  = (const float*)d_in[3];
    const float* W2f  = (const float*)d_in[4];
    const float* b1   = (const float*)d_in[5];
    const float* b2   = (const float*)d_in[6];
    const float* db1  = (const float*)d_in[7];
    const float* db2  = (const float*)d_in[8];
    const float* craw = (const float*)d_in[9];
    const float* rraw = (const float*)d_in[10];
    const int*   W1i  = (const int*)d_in[11];
    const int*   W2i  = (const int*)d_in[12];
    const void*  W1m  = d_in[13];
    const void*  W2m  = d_in[14];

    bf16 *xhi, *xlo, *W1hi, *W1lo, *W1Thi, *W1Tlo, *W2hi, *W2lo, *W2Thi, *W2Tlo;
    bf16 *z1hi, *z1lo, *zhi, *zlo, *thi, *tlo;
    cudaGetSymbolAddress((void**)&xhi,  g_xhi);   cudaGetSymbolAddress((void**)&xlo,  g_xlo);
    cudaGetSymbolAddress((void**)&W1hi, g_W1hi);  cudaGetSymbolAddress((void**)&W1lo, g_W1lo);
    cudaGetSymbolAddress((void**)&W1Thi,g_W1Thi); cudaGetSymbolAddress((void**)&W1Tlo,g_W1Tlo);
    cudaGetSymbolAddress((void**)&W2hi, g_W2hi);  cudaGetSymbolAddress((void**)&W2lo, g_W2lo);
    cudaGetSymbolAddress((void**)&W2Thi,g_W2Thi); cudaGetSymbolAddress((void**)&W2Tlo,g_W2Tlo);
    cudaGetSymbolAddress((void**)&z1hi, g_z1hi);  cudaGetSymbolAddress((void**)&z1lo, g_z1lo);
    cudaGetSymbolAddress((void**)&zhi,  g_zhi);   cudaGetSymbolAddress((void**)&zlo,  g_zlo);
    cudaGetSymbolAddress((void**)&thi,  g_thi);   cudaGetSymbolAddress((void**)&tlo,  g_tlo);

    float* dec = (float*)d_out;
    float* z   = (float*)d_out + (size_t)NBATCH * IN_DIM;

    cudaFuncSetAttribute(gemm_split_kernel,
                         cudaFuncAttributeMaxDynamicSharedMemorySize, SMEM_TOTAL);

    // 1. mask dtype probe
    detect_mask_kernel<<<1, 256>>>((const unsigned int*)W1m, 4096);

    // 2. split x, dequant+split weights (with transposes)
    {
        size_t n = (size_t)NBATCH * IN_DIM;
        split_kernel<<<(unsigned)((n + 255) / 256), 256>>>(x, xhi, xlo, n);
    }
    dequant_split_kernel<<<dim3(HDIM / 32, IN_DIM / 32), dim3(32, 8)>>>(
        W1i, W1m, W1f, cb1, W1hi, W1lo, W1Thi, W1Tlo, IN_DIM, HDIM);
    dequant_split_kernel<<<dim3(OUT_DIM / 32, HDIM / 32), dim3(32, 8)>>>(
        W2i, W2m, W2f, cb2, W2hi, W2lo, W2Thi, W2Tlo, HDIM, OUT_DIM);

    // 3. G1: z1 = c19(x @ W1 + b1)  -> split bf16 only
    gemm_split_kernel<<<dim3(HDIM / BN, NBATCH / BM), 256, SMEM_TOTAL>>>(
        xhi, xlo, W1Thi, W1Tlo, NBATCH, HDIM, IN_DIM,
        b1, 1, craw, rraw, nullptr, z1hi, z1lo);

    // 4. G2: z = z1 @ W2 + b2  -> fp32 output + split
    gemm_split_kernel<<<dim3(OUT_DIM / BN, NBATCH / BM), 256, SMEM_TOTAL>>>(
        z1hi, z1lo, W2Thi, W2Tlo, NBATCH, OUT_DIM, HDIM,
        b2, 0, nullptr, nullptr, z, zhi, zlo);

    // 5. G3: t = z @ W2^T + db1  -> split only
    gemm_split_kernel<<<dim3(HDIM / BN, NBATCH / BM), 256, SMEM_TOTAL>>>(
        zhi, zlo, W2hi, W2lo, NBATCH, HDIM, OUT_DIM,
        db1, 0, nullptr, nullptr, nullptr, thi, tlo);

    // 6. G4: dec = t @ W1^T + db2  -> fp32 output
    gemm_split_kernel<<<dim3(IN_DIM / BN, NBATCH / BM), 256, SMEM_TOTAL>>>(
        thi, tlo, W1hi, W1lo, NBATCH, IN_DIM, HDIM,
        db2, 0, nullptr, nullptr, dec, nullptr, nullptr);
}

// round 5
// speedup vs baseline: 1.9239x; 1.2043x over previous
#include <cuda_runtime.h>
#include <cuda_bf16.h>
#include <cstdint>

#define IN_DIM  2048
#define HDIM    8192
#define OUT_DIM 512
#define NBATCH  4096

typedef __nv_bfloat16 bf16;

// ---------------- scratch (static __device__ per harness rules) ----------------
__device__ __align__(256) bf16 g_xhi [(size_t)NBATCH * IN_DIM];
__device__ __align__(256) bf16 g_xlo [(size_t)NBATCH * IN_DIM];
__device__ __align__(256) bf16 g_W1hi[(size_t)IN_DIM * HDIM];
__device__ __align__(256) bf16 g_W1lo[(size_t)IN_DIM * HDIM];
__device__ __align__(256) bf16 g_W1Thi[(size_t)HDIM * IN_DIM];
__device__ __align__(256) bf16 g_W1Tlo[(size_t)HDIM * IN_DIM];
__device__ __align__(256) bf16 g_W2hi[(size_t)HDIM * OUT_DIM];
__device__ __align__(256) bf16 g_W2lo[(size_t)HDIM * OUT_DIM];
__device__ __align__(256) bf16 g_W2Thi[(size_t)OUT_DIM * HDIM];
__device__ __align__(256) bf16 g_W2Tlo[(size_t)OUT_DIM * HDIM];
__device__ __align__(256) bf16 g_z1hi[(size_t)NBATCH * HDIM];
__device__ __align__(256) bf16 g_z1lo[(size_t)NBATCH * HDIM];
__device__ __align__(256) bf16 g_zhi [(size_t)NBATCH * OUT_DIM];
__device__ __align__(256) bf16 g_zlo [(size_t)NBATCH * OUT_DIM];
__device__ __align__(256) bf16 g_thi [(size_t)NBATCH * HDIM];
__device__ __align__(256) bf16 g_tlo [(size_t)NBATCH * HDIM];
__device__ int g_maskmode;

// ---------------- PTX helpers (compute_100-safe) ----------------
__device__ __forceinline__ uint32_t smem_u32(const void* p) {
    uint32_t a;
    asm("{ .reg .u64 t; cvta.to.shared.u64 t, %1; cvt.u32.u64 %0, t; }" : "=r"(a) : "l"(p));
    return a;
}
#define SWZ128(off) ((off) ^ (((off) >> 3) & 0x70))

__device__ __forceinline__ void cp16(uint32_t dst, const void* src) {
    asm volatile("cp.async.cg.shared.global [%0], [%1], 16;" :: "r"(dst), "l"(src));
}
#define CP_COMMIT() asm volatile("cp.async.commit_group;" ::: "memory")
#define CP_WAIT(n)  asm volatile("cp.async.wait_group %0;" :: "n"(n) : "memory")

__device__ __forceinline__ void ldsm4(uint32_t a, uint32_t& r0, uint32_t& r1,
                                      uint32_t& r2, uint32_t& r3) {
    asm volatile("ldmatrix.sync.aligned.m8n8.x4.shared.b16 {%0,%1,%2,%3}, [%4];"
                 : "=r"(r0), "=r"(r1), "=r"(r2), "=r"(r3) : "r"(a));
}

__device__ __forceinline__ void mma16816(float* d, const uint32_t* a, const uint32_t* b) {
    asm volatile("mma.sync.aligned.m16n8k16.row.col.f32.bf16.bf16.f32 "
        "{%0,%1,%2,%3}, {%4,%5,%6,%7}, {%8,%9}, {%0,%1,%2,%3};"
        : "+f"(d[0]), "+f"(d[1]), "+f"(d[2]), "+f"(d[3])
        : "r"(a[0]), "r"(a[1]), "r"(a[2]), "r"(a[3]), "r"(b[0]), "r"(b[1]));
}

// ---------------- mask dtype detection ----------------
__global__ void detect_mask_kernel(const unsigned int* __restrict__ m, int nwords) {
    __shared__ int ok[4];
    if (threadIdx.x < 4) ok[threadIdx.x] = 1;
    __syncthreads();
    for (int i = threadIdx.x; i < nwords; i += blockDim.x) {
        unsigned w = m[i];
        if (!(w == 0u || w == 1u))          atomicAnd(&ok[0], 0);
        if (!(w == 0u || w == 0x3F800000u)) atomicAnd(&ok[1], 0);
        unsigned lo = w & 0xFFFFu, hi = w >> 16;
        if (!((lo == 0u || lo == 0x3F80u) && (hi == 0u || hi == 0x3F80u))) atomicAnd(&ok[2], 0);
        if (!((lo == 0u || lo == 0x3C00u) && (hi == 0u || hi == 0x3C00u))) atomicAnd(&ok[3], 0);
    }
    __syncthreads();
    if (threadIdx.x == 0) {
        int mode = 0;
        if      (ok[0]) mode = 1;
        else if (ok[1]) mode = 2;
        else if (ok[2]) mode = 3;
        else if (ok[3]) mode = 4;
        g_maskmode = mode;
    }
}

__device__ __forceinline__ int read_mask(const void* p, long i, int mode) {
    switch (mode) {
        case 1:  return ((const int*)p)[i] != 0;
        case 2:  return ((const float*)p)[i] != 0.0f;
        case 3:  return ((const unsigned short*)p)[i] != 0;
        case 4:  return ((const unsigned short*)p)[i] != 0;
        default: return ((const unsigned char*)p)[i] != 0;
    }
}

__device__ __forceinline__ void split2(float v, bf16& h, bf16& l) {
    h = __float2bfloat16(v);
    l = __float2bfloat16(v - __bfloat162float(h));
}

// ---------------- split x ----------------
__global__ void split_kernel(const float* __restrict__ src, bf16* __restrict__ hi,
                             bf16* __restrict__ lo, size_t n) {
    size_t i = (size_t)blockIdx.x * blockDim.x + threadIdx.x;
    if (i < n) {
        bf16 h, l;
        split2(src[i], h, l);
        hi[i] = h; lo[i] = l;
    }
}

// ---------------- dequant + split + transpose ----------------
__global__ void dequant_split_kernel(const int* __restrict__ idx, const void* __restrict__ mask,
                                     const float* __restrict__ wf, const float* __restrict__ cb,
                                     bf16* __restrict__ Whi, bf16* __restrict__ Wlo,
                                     bf16* __restrict__ WThi, bf16* __restrict__ WTlo,
                                     int R, int C) {
    __shared__ float tile[32][33];
    const int mode = g_maskmode;
    const int c0 = blockIdx.x * 32;
    const int r0 = blockIdx.y * 32;
    for (int rr = threadIdx.y; rr < 32; rr += 8) {
        long off = (long)(r0 + rr) * C + c0 + threadIdx.x;
        int  m = read_mask(mask, off, mode);
        float v = m ? cb[idx[off]] : wf[off];
        bf16 h, l; split2(v, h, l);
        Whi[off] = h; Wlo[off] = l;
        tile[rr][threadIdx.x] = v;
    }
    __syncthreads();
    for (int rr = threadIdx.y; rr < 32; rr += 8) {
        float v = tile[threadIdx.x][rr];
        long off = (long)(c0 + rr) * R + r0 + threadIdx.x;
        bf16 h, l; split2(v, h, l);
        WThi[off] = h; WTlo[off] = l;
    }
}

// ---------------- c19 activation ----------------
__device__ __forceinline__ float c19f(float x, float craw, float rhoraw) {
    float c   = fmaxf(craw, 0.1f);
    float rho = fmaxf(rhoraw, 0.0f);
    float L   = 6.0f * c;
    float s   = x / c;
    float n   = floorf(s);
    float t   = s - n;
    float h   = t * (1.0f - t);
    float sgn = (fmodf(n, 2.0f) == 0.0f) ? 1.0f : -1.0f;
    float interior = c * (sgn * h + rho * h * h);
    return (x >= L) ? (x - L) : ((x <= -L) ? (x + L) : interior);
}

// ---------------- mma.sync split-bf16 GEMM (templated N tile) ----------------
// C[M,Nn] = sum over 3 passes A_p[M,K] * B_p[Nn,K]^T  (B K-major)
// passes: (Ahi,Bhi), (Ahi,Blo), (Alo,Bhi)
// Block 128 x (NI*32). 8 warps: 2(M) x 4(N); warp tile 64 x (NI*8). BK=32.
#define BM 128
#define BKK 32
#define NSTAGE 4

template<int NI>   // warp N-tile = NI*8, block N = NI*32.  NI=8 -> 256, NI=4 -> 128
__global__ void __launch_bounds__(256, 1)
gemm_split_kernel(const bf16* __restrict__ Ahi, const bf16* __restrict__ Alo,
                  const bf16* __restrict__ Bhi, const bf16* __restrict__ Blo,
                  int M, int Nn, int K,
                  const float* __restrict__ bias, int epi,
                  const float* __restrict__ craw, const float* __restrict__ rho,
                  float* __restrict__ Cf, bf16* __restrict__ Chi, bf16* __restrict__ Clo) {
    constexpr int BN = NI * 32;
    constexpr int STAGE_BYTES = BM * 64 + BN * 64;
    extern __shared__ char smem[];
    const uint32_t sbase = smem_u32(smem);
    const uint32_t tbase = (sbase + 1023u) & ~1023u;   // 1024B align for swizzle
    const int tid  = threadIdx.x;
    const int wid  = tid >> 5;
    const int lane = tid & 31;
    const int wm = wid & 1;          // M offset wm*64
    const int wn = wid >> 1;         // N offset wn*(NI*8)

    const int m0 = blockIdx.y * BM;
    const int n0 = blockIdx.x * BN;

    uint32_t sA[NSTAGE], sB[NSTAGE];
#pragma unroll
    for (int s = 0; s < NSTAGE; s++) {
        sA[s] = tbase + s * STAGE_BYTES;
        sB[s] = sA[s] + BM * 64;
    }

    const int kchunks = K / BKK;
    const int ITERS = 3 * kchunks;

    float acc[4][NI][4];
#pragma unroll
    for (int i = 0; i < 4; i++)
#pragma unroll
        for (int j = 0; j < NI; j++)
#pragma unroll
            for (int r = 0; r < 4; r++) acc[i][j][r] = 0.0f;

    auto fill = [&](int it) {
        const int p  = it / kchunks;
        const int kc = it % kchunks;
        const bf16* Ap = (p == 2) ? Alo : Ahi;
        const bf16* Bp = (p == 1) ? Blo : Bhi;
        const int s = it % NSTAGE;
        const size_t k0 = (size_t)kc * BKK;
        // A: 128 rows x 4 chunks of 16B = 512 chunks, 2 per thread
#pragma unroll
        for (int i = 0; i < 2; i++) {
            int ch = tid + i * 256;
            int r = ch >> 2, c = ch & 3;
            const char* srcA = (const char*)(Ap + (size_t)(m0 + r) * K + k0) + c * 16;
            cp16(sA[s] + SWZ128(r * 64 + c * 16), srcA);
        }
        // B: BN rows x 4 chunks = NI*128 chunks, NI/2 per thread
#pragma unroll
        for (int i = 0; i < NI / 2; i++) {
            int ch = tid + i * 256;
            int r = ch >> 2, c = ch & 3;
            const char* srcB = (const char*)(Bp + (size_t)(n0 + r) * K + k0) + c * 16;
            cp16(sB[s] + SWZ128(r * 64 + c * 16), srcB);
        }
    };

    // prologue
    for (int it = 0; it < NSTAGE - 1; it++) { fill(it); CP_COMMIT(); }

    for (int it = 0; it < ITERS; it++) {
        CP_WAIT(NSTAGE - 2);
        __syncthreads();
        if (it + NSTAGE - 1 < ITERS) fill(it + NSTAGE - 1);
        CP_COMMIT();

        const int s = it % NSTAGE;
        const uint32_t Ab = sA[s], Bb = sB[s];
#pragma unroll
        for (int kk = 0; kk < 2; kk++) {      // two k16 steps per BK=32
            uint32_t af[4][4];
#pragma unroll
            for (int mi = 0; mi < 4; mi++) {
                int row = wm * 64 + mi * 16 + (lane & 15);
                int ch  = kk * 2 + (lane >> 4);
                ldsm4(Ab + SWZ128(row * 64 + ch * 16),
                      af[mi][0], af[mi][1], af[mi][2], af[mi][3]);
            }
            uint32_t bfr[NI][2];
#pragma unroll
            for (int p = 0; p < NI / 2; p++) {
                int g   = lane >> 3;                       // 8-lane group 0..3
                int ni  = p * 2 + (g >> 1);
                int row = wn * (NI * 8) + ni * 8 + (lane & 7);
                int ch  = kk * 2 + (g & 1);
                uint32_t r0, r1, r2, r3;
                ldsm4(Bb + SWZ128(row * 64 + ch * 16), r0, r1, r2, r3);
                bfr[p * 2][0] = r0;  bfr[p * 2][1] = r1;
                bfr[p * 2 + 1][0] = r2; bfr[p * 2 + 1][1] = r3;
            }
#pragma unroll
            for (int mi = 0; mi < 4; mi++)
#pragma unroll
                for (int ni = 0; ni < NI; ni++)
                    mma16816(acc[mi][ni], af[mi], bfr[ni]);
        }
    }

    // ---------------- epilogue: bias (+c19) + outputs ----------------
#pragma unroll
    for (int ni = 0; ni < NI; ni++) {
        const int n = n0 + wn * (NI * 8) + ni * 8 + 2 * (lane & 3);
        const float bv0 = __ldg(bias + n), bv1 = __ldg(bias + n + 1);
        float c0 = 0, c1 = 0, r0 = 0, r1 = 0;
        if (epi) {
            c0 = __ldg(craw + n);  c1 = __ldg(craw + n + 1);
            r0 = __ldg(rho + n);   r1 = __ldg(rho + n + 1);
        }
#pragma unroll
        for (int mi = 0; mi < 4; mi++) {
#pragma unroll
            for (int h = 0; h < 2; h++) {
                const int m = m0 + wm * 64 + mi * 16 + (lane >> 2) + h * 8;
                float v0 = acc[mi][ni][2 * h]     + bv0;
                float v1 = acc[mi][ni][2 * h + 1] + bv1;
                if (epi) { v0 = c19f(v0, c0, r0); v1 = c19f(v1, c1, r1); }
                const size_t off = (size_t)m * Nn + n;
                if (Cf) *(float2*)(Cf + off) = make_float2(v0, v1);
                if (Chi) {
                    bf16 h0, l0, h1, l1;
                    split2(v0, h0, l0); split2(v1, h1, l1);
                    *(__nv_bfloat162*)(Chi + off) = __nv_bfloat162(h0, h1);
                    *(__nv_bfloat162*)(Clo + off) = __nv_bfloat162(l0, l1);
                }
            }
        }
    }
}

#define SMEM_FOR(NI) (1024 + NSTAGE * (BM * 64 + (NI) * 32 * 64))

// ---------------- launch ----------------
extern "C" void kernel_launch(void* const* d_in, const int* in_sizes, int n_in,
                              void* d_out, int out_size) {
    const float* x    = (const float*)d_in[0];
    const float* cb1  = (const float*)d_in[1];
    const float* cb2  = (const float*)d_in[2];
    const float* W1f  = (const float*)d_in[3];
    const float* W2f  = (const float*)d_in[4];
    const float* b1   = (const float*)d_in[5];
    const float* b2   = (const float*)d_in[6];
    const float* db1  = (const float*)d_in[7];
    const float* db2  = (const float*)d_in[8];
    const float* craw = (const float*)d_in[9];
    const float* rraw = (const float*)d_in[10];
    const int*   W1i  = (const int*)d_in[11];
    const int*   W2i  = (const int*)d_in[12];
    const void*  W1m  = d_in[13];
    const void*  W2m  = d_in[14];

    bf16 *xhi, *xlo, *W1hi, *W1lo, *W1Thi, *W1Tlo, *W2hi, *W2lo, *W2Thi, *W2Tlo;
    bf16 *z1hi, *z1lo, *zhi, *zlo, *thi, *tlo;
    cudaGetSymbolAddress((void**)&xhi,  g_xhi);   cudaGetSymbolAddress((void**)&xlo,  g_xlo);
    cudaGetSymbolAddress((void**)&W1hi, g_W1hi);  cudaGetSymbolAddress((void**)&W1lo, g_W1lo);
    cudaGetSymbolAddress((void**)&W1Thi,g_W1Thi); cudaGetSymbolAddress((void**)&W1Tlo,g_W1Tlo);
    cudaGetSymbolAddress((void**)&W2hi, g_W2hi);  cudaGetSymbolAddress((void**)&W2lo, g_W2lo);
    cudaGetSymbolAddress((void**)&W2Thi,g_W2Thi); cudaGetSymbolAddress((void**)&W2Tlo,g_W2Tlo);
    cudaGetSymbolAddress((void**)&z1hi, g_z1hi);  cudaGetSymbolAddress((void**)&z1lo, g_z1lo);
    cudaGetSymbolAddress((void**)&zhi,  g_zhi);   cudaGetSymbolAddress((void**)&zlo,  g_zlo);
    cudaGetSymbolAddress((void**)&thi,  g_thi);   cudaGetSymbolAddress((void**)&tlo,  g_tlo);

    float* dec = (float*)d_out;
    float* z   = (float*)d_out + (size_t)NBATCH * IN_DIM;

    cudaFuncSetAttribute(gemm_split_kernel<8>,
                         cudaFuncAttributeMaxDynamicSharedMemorySize, SMEM_FOR(8));
    cudaFuncSetAttribute(gemm_split_kernel<4>,
                         cudaFuncAttributeMaxDynamicSharedMemorySize, SMEM_FOR(4));

    // 1. mask dtype probe
    detect_mask_kernel<<<1, 256>>>((const unsigned int*)W1m, 4096);

    // 2. split x, dequant+split weights (with transposes)
    {
        size_t n = (size_t)NBATCH * IN_DIM;
        split_kernel<<<(unsigned)((n + 255) / 256), 256>>>(x, xhi, xlo, n);
    }
    dequant_split_kernel<<<dim3(HDIM / 32, IN_DIM / 32), dim3(32, 8)>>>(
        W1i, W1m, W1f, cb1, W1hi, W1lo, W1Thi, W1Tlo, IN_DIM, HDIM);
    dequant_split_kernel<<<dim3(OUT_DIM / 32, HDIM / 32), dim3(32, 8)>>>(
        W2i, W2m, W2f, cb2, W2hi, W2lo, W2Thi, W2Tlo, HDIM, OUT_DIM);

    // 3. G1: z1 = c19(x @ W1 + b1)  -> split bf16 only   [4096 x 8192]
    gemm_split_kernel<8><<<dim3(HDIM / 256, NBATCH / BM), 256, SMEM_FOR(8)>>>(
        xhi, xlo, W1Thi, W1Tlo, NBATCH, HDIM, IN_DIM,
        b1, 1, craw, rraw, nullptr, z1hi, z1lo);

    // 4. G2: z = z1 @ W2 + b2  -> fp32 output + split    [4096 x 512]
    gemm_split_kernel<4><<<dim3(OUT_DIM / 128, NBATCH / BM), 256, SMEM_FOR(4)>>>(
        z1hi, z1lo, W2Thi, W2Tlo, NBATCH, OUT_DIM, HDIM,
        b2, 0, nullptr, nullptr, z, zhi, zlo);

    // 5. G3: t = z @ W2^T + db1  -> split only           [4096 x 8192]
    gemm_split_kernel<8><<<dim3(HDIM / 256, NBATCH / BM), 256, SMEM_FOR(8)>>>(
        zhi, zlo, W2hi, W2lo, NBATCH, HDIM, OUT_DIM,
        db1, 0, nullptr, nullptr, nullptr, thi, tlo);

    // 6. G4: dec = t @ W1^T + db2  -> fp32 output        [4096 x 2048]
    gemm_split_kernel<8><<<dim3(IN_DIM / 256, NBATCH / BM), 256, SMEM_FOR(8)>>>(
        thi, tlo, W1hi, W1lo, NBATCH, IN_DIM, HDIM,
        db2, 0, nullptr, nullptr, dec, nullptr, nullptr);
}

// round 6
// speedup vs baseline: 2.0587x; 1.0701x over previous
#include <cuda_runtime.h>
#include <cuda_bf16.h>
#include <cstdint>

#define IN_DIM  2048
#define HDIM    8192
#define OUT_DIM 512
#define NBATCH  4096

typedef __nv_bfloat16 bf16;

// ---------------- scratch (static __device__ per harness rules) ----------------
__device__ __align__(256) bf16 g_xhi [(size_t)NBATCH * IN_DIM];
__device__ __align__(256) bf16 g_xlo [(size_t)NBATCH * IN_DIM];
__device__ __align__(256) bf16 g_W1hi[(size_t)IN_DIM * HDIM];
__device__ __align__(256) bf16 g_W1lo[(size_t)IN_DIM * HDIM];
__device__ __align__(256) bf16 g_W1Thi[(size_t)HDIM * IN_DIM];
__device__ __align__(256) bf16 g_W1Tlo[(size_t)HDIM * IN_DIM];
__device__ __align__(256) bf16 g_W2hi[(size_t)HDIM * OUT_DIM];
__device__ __align__(256) bf16 g_W2lo[(size_t)HDIM * OUT_DIM];
__device__ __align__(256) bf16 g_W2Thi[(size_t)OUT_DIM * HDIM];
__device__ __align__(256) bf16 g_W2Tlo[(size_t)OUT_DIM * HDIM];
__device__ __align__(256) bf16 g_z1hi[(size_t)NBATCH * HDIM];
__device__ __align__(256) bf16 g_z1lo[(size_t)NBATCH * HDIM];
__device__ __align__(256) bf16 g_zhi [(size_t)NBATCH * OUT_DIM];
__device__ __align__(256) bf16 g_zlo [(size_t)NBATCH * OUT_DIM];
__device__ __align__(256) bf16 g_thi [(size_t)NBATCH * HDIM];
__device__ __align__(256) bf16 g_tlo [(size_t)NBATCH * HDIM];
__device__ int g_maskmode;

// ---------------- PTX helpers (compute_100-safe) ----------------
__device__ __forceinline__ uint32_t smem_u32(const void* p) {
    uint32_t a;
    asm("{ .reg .u64 t; cvta.to.shared.u64 t, %1; cvt.u32.u64 %0, t; }" : "=r"(a) : "l"(p));
    return a;
}
#define SWZ128(off) ((off) ^ (((off) >> 3) & 0x70))

__device__ __forceinline__ void cp16(uint32_t dst, const void* src) {
    asm volatile("cp.async.cg.shared.global [%0], [%1], 16;" :: "r"(dst), "l"(src));
}
#define CP_COMMIT() asm volatile("cp.async.commit_group;" ::: "memory")
#define CP_WAIT(n)  asm volatile("cp.async.wait_group %0;" :: "n"(n) : "memory")

__device__ __forceinline__ void ldsm4(uint32_t a, uint32_t& r0, uint32_t& r1,
                                      uint32_t& r2, uint32_t& r3) {
    asm volatile("ldmatrix.sync.aligned.m8n8.x4.shared.b16 {%0,%1,%2,%3}, [%4];"
                 : "=r"(r0), "=r"(r1), "=r"(r2), "=r"(r3) : "r"(a));
}

__device__ __forceinline__ void mma16816(float* d, const uint32_t* a, const uint32_t* b) {
    asm volatile("mma.sync.aligned.m16n8k16.row.col.f32.bf16.bf16.f32 "
        "{%0,%1,%2,%3}, {%4,%5,%6,%7}, {%8,%9}, {%0,%1,%2,%3};"
        : "+f"(d[0]), "+f"(d[1]), "+f"(d[2]), "+f"(d[3])
        : "r"(a[0]), "r"(a[1]), "r"(a[2]), "r"(a[3]), "r"(b[0]), "r"(b[1]));
}

// ---------------- mask dtype detection ----------------
__global__ void detect_mask_kernel(const unsigned int* __restrict__ m, int nwords) {
    __shared__ int ok[4];
    if (threadIdx.x < 4) ok[threadIdx.x] = 1;
    __syncthreads();
    for (int i = threadIdx.x; i < nwords; i += blockDim.x) {
        unsigned w = m[i];
        if (!(w == 0u || w == 1u))          atomicAnd(&ok[0], 0);
        if (!(w == 0u || w == 0x3F800000u)) atomicAnd(&ok[1], 0);
        unsigned lo = w & 0xFFFFu, hi = w >> 16;
        if (!((lo == 0u || lo == 0x3F80u) && (hi == 0u || hi == 0x3F80u))) atomicAnd(&ok[2], 0);
        if (!((lo == 0u || lo == 0x3C00u) && (hi == 0u || hi == 0x3C00u))) atomicAnd(&ok[3], 0);
    }
    __syncthreads();
    if (threadIdx.x == 0) {
        int mode = 0;
        if      (ok[0]) mode = 1;
        else if (ok[1]) mode = 2;
        else if (ok[2]) mode = 3;
        else if (ok[3]) mode = 4;
        g_maskmode = mode;
    }
}

__device__ __forceinline__ int read_mask(const void* p, long i, int mode) {
    switch (mode) {
        case 1:  return ((const int*)p)[i] != 0;
        case 2:  return ((const float*)p)[i] != 0.0f;
        case 3:  return ((const unsigned short*)p)[i] != 0;
        case 4:  return ((const unsigned short*)p)[i] != 0;
        default: return ((const unsigned char*)p)[i] != 0;
    }
}

__device__ __forceinline__ void split2(float v, bf16& h, bf16& l) {
    h = __float2bfloat16(v);
    l = __float2bfloat16(v - __bfloat162float(h));
}

// ---------------- split x ----------------
__global__ void split_kernel(const float* __restrict__ src, bf16* __restrict__ hi,
                             bf16* __restrict__ lo, size_t n) {
    size_t i = (size_t)blockIdx.x * blockDim.x + threadIdx.x;
    if (i < n) {
        bf16 h, l;
        split2(src[i], h, l);
        hi[i] = h; lo[i] = l;
    }
}

// ---------------- dequant + split + transpose ----------------
__global__ void dequant_split_kernel(const int* __restrict__ idx, const void* __restrict__ mask,
                                     const float* __restrict__ wf, const float* __restrict__ cb,
                                     bf16* __restrict__ Whi, bf16* __restrict__ Wlo,
                                     bf16* __restrict__ WThi, bf16* __restrict__ WTlo,
                                     int R, int C) {
    __shared__ float tile[32][33];
    const int mode = g_maskmode;
    const int c0 = blockIdx.x * 32;
    const int r0 = blockIdx.y * 32;
    for (int rr = threadIdx.y; rr < 32; rr += 8) {
        long off = (long)(r0 + rr) * C + c0 + threadIdx.x;
        int  m = read_mask(mask, off, mode);
        float v = m ? cb[idx[off]] : wf[off];
        bf16 h, l; split2(v, h, l);
        Whi[off] = h; Wlo[off] = l;
        tile[rr][threadIdx.x] = v;
    }
    __syncthreads();
    for (int rr = threadIdx.y; rr < 32; rr += 8) {
        float v = tile[threadIdx.x][rr];
        long off = (long)(c0 + rr) * R + r0 + threadIdx.x;
        bf16 h, l; split2(v, h, l);
        WThi[off] = h; WTlo[off] = l;
    }
}

// ---------------- c19 activation ----------------
__device__ __forceinline__ float c19f(float x, float craw, float rhoraw) {
    float c   = fmaxf(craw, 0.1f);
    float rho = fmaxf(rhoraw, 0.0f);
    float L   = 6.0f * c;
    float s   = x / c;
    float n   = floorf(s);
    float t   = s - n;
    float h   = t * (1.0f - t);
    float sgn = (fmodf(n, 2.0f) == 0.0f) ? 1.0f : -1.0f;
    float interior = c * (sgn * h + rho * h * h);
    return (x >= L) ? (x - L) : ((x <= -L) ? (x + L) : interior);
}

// ---------------- mma.sync split-bf16 GEMM (pipelined frags) ----------------
// C[M,Nn] = sum over 3 passes A_p[M,K] * B_p[Nn,K]^T  (B K-major)
// passes: (Ahi,Bhi), (Ahi,Blo), (Alo,Bhi)
// Block 128 x (NI*32). 8 warps: 2(M) x 4(N); warp tile 64 x (NI*8). BK=32.
// NSTAGE=5 with wait_group(2): stages it AND it+1 resident -> cross-iteration
// register-level fragment prefetch (LDSM latency hidden behind MMA issue).
#define BM 128
#define BKK 32
#define NSTAGE 5

template<int NI>   // warp N-tile = NI*8, block N = NI*32.  NI=8 -> 256, NI=4 -> 128
__global__ void __launch_bounds__(256, 1)
gemm_split_kernel(const bf16* __restrict__ Ahi, const bf16* __restrict__ Alo,
                  const bf16* __restrict__ Bhi, const bf16* __restrict__ Blo,
                  int M, int Nn, int K,
                  const float* __restrict__ bias, int epi,
                  const float* __restrict__ craw, const float* __restrict__ rho,
                  float* __restrict__ Cf, bf16* __restrict__ Chi, bf16* __restrict__ Clo) {
    constexpr int BN = NI * 32;
    constexpr int STAGE_BYTES = BM * 64 + BN * 64;
    extern __shared__ char smem[];
    const uint32_t sbase = smem_u32(smem);
    const uint32_t tbase = (sbase + 1023u) & ~1023u;   // 1024B align for swizzle
    const int tid  = threadIdx.x;
    const int wid  = tid >> 5;
    const int lane = tid & 31;
    const int wm = wid & 1;          // M offset wm*64
    const int wn = wid >> 1;         // N offset wn*(NI*8)

    const int m0 = blockIdx.y * BM;
    const int n0 = blockIdx.x * BN;

    uint32_t sA[NSTAGE], sB[NSTAGE];
#pragma unroll
    for (int s = 0; s < NSTAGE; s++) {
        sA[s] = tbase + s * STAGE_BYTES;
        sB[s] = sA[s] + BM * 64;
    }

    const int kchunks = K / BKK;
    const int ITERS = 3 * kchunks;

    float acc[4][NI][4];
#pragma unroll
    for (int i = 0; i < 4; i++)
#pragma unroll
        for (int j = 0; j < NI; j++)
#pragma unroll
            for (int r = 0; r < 4; r++) acc[i][j][r] = 0.0f;

    auto fill = [&](int it) {
        const int p  = it / kchunks;
        const int kc = it % kchunks;
        const bf16* Ap = (p == 2) ? Alo : Ahi;
        const bf16* Bp = (p == 1) ? Blo : Bhi;
        const int s = it % NSTAGE;
        const size_t k0 = (size_t)kc * BKK;
#pragma unroll
        for (int i = 0; i < 2; i++) {
            int ch = tid + i * 256;
            int r = ch >> 2, c = ch & 3;
            const char* srcA = (const char*)(Ap + (size_t)(m0 + r) * K + k0) + c * 16;
            cp16(sA[s] + SWZ128(r * 64 + c * 16), srcA);
        }
#pragma unroll
        for (int i = 0; i < NI / 2; i++) {
            int ch = tid + i * 256;
            int r = ch >> 2, c = ch & 3;
            const char* srcB = (const char*)(Bp + (size_t)(n0 + r) * K + k0) + c * 16;
            cp16(sB[s] + SWZ128(r * 64 + c * 16), srcB);
        }
    };

    // register frag double buffers
    uint32_t af[2][4][4];
    uint32_t bfr[2][NI][2];

    auto load_frags = [&](int b, uint32_t Ab, uint32_t Bb, int kk) {
#pragma unroll
        for (int mi = 0; mi < 4; mi++) {
            int row = wm * 64 + mi * 16 + (lane & 15);
            int ch  = kk * 2 + (lane >> 4);
            ldsm4(Ab + SWZ128(row * 64 + ch * 16),
                  af[b][mi][0], af[b][mi][1], af[b][mi][2], af[b][mi][3]);
        }
#pragma unroll
        for (int p = 0; p < NI / 2; p++) {
            int g   = lane >> 3;
            int ni  = p * 2 + (g >> 1);
            int row = wn * (NI * 8) + ni * 8 + (lane & 7);
            int ch  = kk * 2 + (g & 1);
            uint32_t r0, r1, r2, r3;
            ldsm4(Bb + SWZ128(row * 64 + ch * 16), r0, r1, r2, r3);
            bfr[b][p * 2][0] = r0;  bfr[b][p * 2][1] = r1;
            bfr[b][p * 2 + 1][0] = r2; bfr[b][p * 2 + 1][1] = r3;
        }
    };

    auto mma_all = [&](int b) {
#pragma unroll
        for (int mi = 0; mi < 4; mi++)
#pragma unroll
            for (int ni = 0; ni < NI; ni++)
                mma16816(acc[mi][ni], af[b][mi], bfr[b][ni]);
    };

    // prologue: fill stages 0..3 (4 commit groups)
    for (int it = 0; it < NSTAGE - 1; it++) { fill(it); CP_COMMIT(); }
    CP_WAIT(3);                 // stage 0 ready
    __syncthreads();
    load_frags(0, sA[0], sB[0], 0);   // frags(it=0, kk=0) -> buf 0

    for (int it = 0; it < ITERS; it++) {
        CP_WAIT(2);             // stages it and it+1 both ready
        __syncthreads();        // all warps done reading the stage fill() overwrites
        if (it + NSTAGE - 1 < ITERS) fill(it + NSTAGE - 1);
        CP_COMMIT();

        const int s  = it % NSTAGE;
        const int s1 = (it + 1) % NSTAGE;

        // kk=0: prefetch kk=1 frags into buf1, MMA on buf0
        load_frags(1, sA[s], sB[s], 1);
        mma_all(0);
        // kk=1: prefetch next-iteration kk=0 frags into buf0, MMA on buf1
        if (it + 1 < ITERS) load_frags(0, sA[s1], sB[s1], 0);
        mma_all(1);
    }

    // ---------------- epilogue: bias (+c19) + outputs ----------------
#pragma unroll
    for (int ni = 0; ni < NI; ni++) {
        const int n = n0 + wn * (NI * 8) + ni * 8 + 2 * (lane & 3);
        const float bv0 = __ldg(bias + n), bv1 = __ldg(bias + n + 1);
        float c0 = 0, c1 = 0, r0 = 0, r1 = 0;
        if (epi) {
            c0 = __ldg(craw + n);  c1 = __ldg(craw + n + 1);
            r0 = __ldg(rho + n);   r1 = __ldg(rho + n + 1);
        }
#pragma unroll
        for (int mi = 0; mi < 4; mi++) {
#pragma unroll
            for (int h = 0; h < 2; h++) {
                const int m = m0 + wm * 64 + mi * 16 + (lane >> 2) + h * 8;
                float v0 = acc[mi][ni][2 * h]     + bv0;
                float v1 = acc[mi][ni][2 * h + 1] + bv1;
                if (epi) { v0 = c19f(v0, c0, r0); v1 = c19f(v1, c1, r1); }
                const size_t off = (size_t)m * Nn + n;
                if (Cf) *(float2*)(Cf + off) = make_float2(v0, v1);
                if (Chi) {
                    bf16 h0, l0, h1, l1;
                    split2(v0, h0, l0); split2(v1, h1, l1);
                    *(__nv_bfloat162*)(Chi + off) = __nv_bfloat162(h0, h1);
                    *(__nv_bfloat162*)(Clo + off) = __nv_bfloat162(l0, l1);
                }
            }
        }
    }
}

#define SMEM_FOR(NI) (1024 + NSTAGE * (BM * 64 + (NI) * 32 * 64))

// ---------------- launch ----------------
extern "C" void kernel_launch(void* const* d_in, const int* in_sizes, int n_in,
                              void* d_out, int out_size) {
    const float* x    = (const float*)d_in[0];
    const float* cb1  = (const float*)d_in[1];
    const float* cb2  = (const float*)d_in[2];
    const float* W1f  = (const float*)d_in[3];
    const float* W2f  = (const float*)d_in[4];
    const float* b1   = (const float*)d_in[5];
    const float* b2   = (const float*)d_in[6];
    const float* db1  = (const float*)d_in[7];
    const float* db2  = (const float*)d_in[8];
    const float* craw = (const float*)d_in[9];
    const float* rraw = (const float*)d_in[10];
    const int*   W1i  = (const int*)d_in[11];
    const int*   W2i  = (const int*)d_in[12];
    const void*  W1m  = d_in[13];
    const void*  W2m  = d_in[14];

    bf16 *xhi, *xlo, *W1hi, *W1lo, *W1Thi, *W1Tlo, *W2hi, *W2lo, *W2Thi, *W2Tlo;
    bf16 *z1hi, *z1lo, *zhi, *zlo, *thi, *tlo;
    cudaGetSymbolAddress((void**)&xhi,  g_xhi);   cudaGetSymbolAddress((void**)&xlo,  g_xlo);
    cudaGetSymbolAddress((void**)&W1hi, g_W1hi);  cudaGetSymbolAddress((void**)&W1lo, g_W1lo);
    cudaGetSymbolAddress((void**)&W1Thi,g_W1Thi); cudaGetSymbolAddress((void**)&W1Tlo,g_W1Tlo);
    cudaGetSymbolAddress((void**)&W2hi, g_W2hi);  cudaGetSymbolAddress((void**)&W2lo, g_W2lo);
    cudaGetSymbolAddress((void**)&W2Thi,g_W2Thi); cudaGetSymbolAddress((void**)&W2Tlo,g_W2Tlo);
    cudaGetSymbolAddress((void**)&z1hi, g_z1hi);  cudaGetSymbolAddress((void**)&z1lo, g_z1lo);
    cudaGetSymbolAddress((void**)&zhi,  g_zhi);   cudaGetSymbolAddress((void**)&zlo,  g_zlo);
    cudaGetSymbolAddress((void**)&thi,  g_thi);   cudaGetSymbolAddress((void**)&tlo,  g_tlo);

    float* dec = (float*)d_out;
    float* z   = (float*)d_out + (size_t)NBATCH * IN_DIM;

    cudaFuncSetAttribute(gemm_split_kernel<8>,
                         cudaFuncAttributeMaxDynamicSharedMemorySize, SMEM_FOR(8));
    cudaFuncSetAttribute(gemm_split_kernel<4>,
                         cudaFuncAttributeMaxDynamicSharedMemorySize, SMEM_FOR(4));

    // 1. mask dtype probe
    detect_mask_kernel<<<1, 256>>>((const unsigned int*)W1m, 4096);

    // 2. split x, dequant+split weights (with transposes)
    {
        size_t n = (size_t)NBATCH * IN_DIM;
        split_kernel<<<(unsigned)((n + 255) / 256), 256>>>(x, xhi, xlo, n);
    }
    dequant_split_kernel<<<dim3(HDIM / 32, IN_DIM / 32), dim3(32, 8)>>>(
        W1i, W1m, W1f, cb1, W1hi, W1lo, W1Thi, W1Tlo, IN_DIM, HDIM);
    dequant_split_kernel<<<dim3(OUT_DIM / 32, HDIM / 32), dim3(32, 8)>>>(
        W2i, W2m, W2f, cb2, W2hi, W2lo, W2Thi, W2Tlo, HDIM, OUT_DIM);

    // 3. G1: z1 = c19(x @ W1 + b1)  -> split bf16 only   [4096 x 8192]
    gemm_split_kernel<8><<<dim3(HDIM / 256, NBATCH / BM), 256, SMEM_FOR(8)>>>(
        xhi, xlo, W1Thi, W1Tlo, NBATCH, HDIM, IN_DIM,
        b1, 1, craw, rraw, nullptr, z1hi, z1lo);

    // 4. G2: z = z1 @ W2 + b2  -> fp32 output + split    [4096 x 512]
    gemm_split_kernel<4><<<dim3(OUT_DIM / 128, NBATCH / BM), 256, SMEM_FOR(4)>>>(
        z1hi, z1lo, W2Thi, W2Tlo, NBATCH, OUT_DIM, HDIM,
        b2, 0, nullptr, nullptr, z, zhi, zlo);

    // 5. G3: t = z @ W2^T + db1  -> split only           [4096 x 8192]
    gemm_split_kernel<8><<<dim3(HDIM / 256, NBATCH / BM), 256, SMEM_FOR(8)>>>(
        zhi, zlo, W2hi, W2lo, NBATCH, HDIM, OUT_DIM,
        db1, 0, nullptr, nullptr, nullptr, thi, tlo);

    // 6. G4: dec = t @ W1^T + db2  -> fp32 output        [4096 x 2048]
    gemm_split_kernel<8><<<dim3(IN_DIM / 256, NBATCH / BM), 256, SMEM_FOR(8)>>>(
        thi, tlo, W1hi, W1lo, NBATCH, IN_DIM, HDIM,
        db2, 0, nullptr, nullptr, dec, nullptr, nullptr);
}